// round 1
// baseline (speedup 1.0000x reference)
#include <cuda_runtime.h>
#include <cuda_bf16.h>

#define TM 32          // batch rows per block
#define TH 256         // threads per block
#define HID 512
#define NIN 16
#define NOUT 136

// smem layout (floats):
//  Xs   [TM*NIN]        = 512
//  H0s  [TM*HID]        = 16384
//  H1s  [TM*HID]        = 16384
//  Ws   [32*HID]        = 16384   (W1 slab; reused for W2 slab / scratch)
#define SMEM_FLOATS (512 + 16384*3)

__global__ __launch_bounds__(TH, 1)
void ptpd_quad_kernel(const float* __restrict__ pts,
                      const float* __restrict__ W0, const float* __restrict__ b0,
                      const float* __restrict__ W1, const float* __restrict__ b1,
                      const float* __restrict__ W2, const float* __restrict__ b2,
                      float* __restrict__ out, int B)
{
    extern __shared__ float smem[];
    float* Xs  = smem;                 // [TM][16]
    float* H0s = Xs  + TM * NIN;       // [TM][512]
    float* H1s = H0s + TM * HID;       // [TM][512]
    float* Ws  = H1s + TM * HID;       // [32][512] slab

    const int tid  = threadIdx.x;
    const int row0 = blockIdx.x * TM;

    // ---- load X tile (coalesced) ----
    for (int i = tid; i < TM * NIN; i += TH)
        Xs[i] = pts[row0 * NIN + i];
    __syncthreads();

    const int c0 = tid;
    const int c1 = tid + 256;

    // ================= Layer 0: [TM,16] @ [16,512] + b0, tanh =================
    {
        float w0a[NIN], w0b[NIN];
        #pragma unroll
        for (int k = 0; k < NIN; k++) {
            w0a[k] = W0[k * HID + c0];
            w0b[k] = W0[k * HID + c1];
        }
        const float ba = b0[c0];
        const float bb = b0[c1];
        #pragma unroll 4
        for (int r = 0; r < TM; r++) {
            float a = ba, b = bb;
            #pragma unroll
            for (int k = 0; k < NIN; k++) {
                const float x = Xs[r * NIN + k];
                a = fmaf(x, w0a[k], a);
                b = fmaf(x, w0b[k], b);
            }
            H0s[r * HID + c0] = tanhf(a);
            H0s[r * HID + c1] = tanhf(b);
        }
    }
    __syncthreads();

    // ================= Layer 1: [TM,512] @ [512,512] + b1, tanh ===============
    {
        float acc0[TM], acc1[TM];
        const float bb1a = b1[c0];
        const float bb1b = b1[c1];
        #pragma unroll
        for (int r = 0; r < TM; r++) { acc0[r] = bb1a; acc1[r] = bb1b; }

        for (int kt = 0; kt < HID; kt += 32) {
            __syncthreads();   // previous slab fully consumed
            // stage W1[kt..kt+32) rows into smem (coalesced)
            const float* gW = W1 + kt * HID;
            #pragma unroll
            for (int i = 0; i < (32 * HID) / TH; i++)
                Ws[tid + i * TH] = gW[tid + i * TH];
            __syncthreads();

            #pragma unroll 2
            for (int kk = 0; kk < 32; kk++) {
                const float wa = Ws[kk * HID + c0];
                const float wb = Ws[kk * HID + c1];
                const int kabs = kt + kk;
                #pragma unroll
                for (int r = 0; r < TM; r++) {
                    const float h = H0s[r * HID + kabs];   // warp broadcast
                    acc0[r] = fmaf(h, wa, acc0[r]);
                    acc1[r] = fmaf(h, wb, acc1[r]);
                }
            }
        }
        #pragma unroll
        for (int r = 0; r < TM; r++) {
            H1s[r * HID + c0] = tanhf(acc0[r]);
            H1s[r * HID + c1] = tanhf(acc1[r]);
        }
    }

    // ================= Layer 2: [TM,512] @ [512,136] + b2 =====================
    // thread -> (row r2 = tid>>3, col group g = tid&7 covering 17 cols)
    const int r2    = tid >> 3;
    const int g     = tid & 7;
    const int cbase = g * 17;
    float acc2[17];
    #pragma unroll
    for (int j = 0; j < 17; j++) acc2[j] = b2[cbase + j];

    for (int kt = 0; kt < HID; kt += 32) {
        __syncthreads();   // previous slab consumed (also fences H1s on first iter)
        // stage W2[kt..kt+32) rows: 32*136 = 4352 floats
        const float* gW = W2 + kt * NOUT;
        for (int i = tid; i < 32 * NOUT; i += TH)
            Ws[i] = gW[i];
        __syncthreads();

        #pragma unroll 2
        for (int kk = 0; kk < 32; kk++) {
            const float h = H1s[r2 * HID + kt + kk];
            #pragma unroll
            for (int j = 0; j < 17; j++)
                acc2[j] = fmaf(h, Ws[kk * NOUT + cbase + j], acc2[j]);
        }
    }

    // write net into smem (reuse H0s region as netS[TM][136])
    float* netS = H0s;
    __syncthreads();
    #pragma unroll
    for (int j = 0; j < 17; j++)
        netS[r2 * NOUT + cbase + j] = acc2[j];
    __syncthreads();

    // ============ quadratic form: val = ||M^T x||^2 + eps*||x||^2 =============
    if (tid < TM) {
        const int r = tid;
        const float* nn = netS + r * NOUT;
        const float* xv = Xs + r * NIN;

        float x[NIN];
        float sx = 0.0f;
        #pragma unroll
        for (int i = 0; i < NIN; i++) { x[i] = xv[i]; sx = fmaf(x[i], x[i], sx); }

        float y[NIN];
        #pragma unroll
        for (int j = 0; j < NIN; j++) y[j] = 0.0f;

        int t = 0;
        #pragma unroll
        for (int i = 0; i < NIN; i++) {
            #pragma unroll
            for (int j = 0; j <= i; j++) {
                y[j] = fmaf(nn[t], x[i], y[j]);
                t++;
            }
        }
        float v = 0.0f;
        #pragma unroll
        for (int j = 0; j < NIN; j++) v = fmaf(y[j], y[j], v);

        out[row0 + r] = v + 1e-6f * sx;
    }
}

extern "C" void kernel_launch(void* const* d_in, const int* in_sizes, int n_in,
                              void* d_out, int out_size)
{
    const float* pts = (const float*)d_in[0];
    const float* W0  = (const float*)d_in[1];
    const float* b0  = (const float*)d_in[2];
    const float* W1  = (const float*)d_in[3];
    const float* b1  = (const float*)d_in[4];
    const float* W2  = (const float*)d_in[5];
    const float* b2  = (const float*)d_in[6];
    float* out = (float*)d_out;

    const int B = in_sizes[0] / NIN;
    const int smem_bytes = SMEM_FLOATS * sizeof(float);

    static bool attr_set = false;  // idempotent attribute, no device state
    cudaFuncSetAttribute(ptpd_quad_kernel,
                         cudaFuncAttributeMaxDynamicSharedMemorySize, smem_bytes);
    (void)attr_set;

    const int grid = (B + TM - 1) / TM;
    ptpd_quad_kernel<<<grid, TH, smem_bytes>>>(pts, W0, b0, W1, b1, W2, b2, out, B);
}

// round 2
// speedup vs baseline: 3.2619x; 3.2619x over previous
#include <cuda_runtime.h>
#include <cuda_bf16.h>
#include <stdint.h>

#define TH 256
#define TM 64
#define HID 512
#define NIN 16
#define NOUT 136
#define NOUTP 144

// smem strides (in bf16 elements unless noted)
#define H0S 520     // H0 row stride  (bank shift 4/row -> conflict-free frags)
#define H1S 136     // H1 chunk row stride
#define WS  72      // weight slab row stride
#define NETS 145    // netS stride (f32)

// smem byte offsets
#define XS_OFF   0                      // 64*16*4      = 4096
#define H0H_OFF  4096                   // 64*520*2     = 66560
#define H0L_OFF  (4096+66560)
#define H1H_OFF  (4096+2*66560)         // 64*136*2     = 17408
#define H1L_OFF  (H1H_OFF+17408)
#define WB_OFF   (H1H_OFF+2*17408)      // 2*144*72*2   = 41472
#define SMEM_BYTES (WB_OFF+41472)       // 213504

// pre-split, pre-transposed weights: [n][k] bf16
__device__ __nv_bfloat16 g_W1hi[HID*HID];
__device__ __nv_bfloat16 g_W1lo[HID*HID];
__device__ __nv_bfloat16 g_W2hi[NOUTP*HID];
__device__ __nv_bfloat16 g_W2lo[NOUTP*HID];

__global__ void prep_weights(const float* __restrict__ W1,
                             const float* __restrict__ W2)
{
    int i = blockIdx.x * blockDim.x + threadIdx.x;
    if (i < HID*HID) {
        int n = i >> 9, k = i & 511;
        float v = W1[k*HID + n];
        __nv_bfloat16 h = __float2bfloat16(v);
        g_W1hi[n*HID + k] = h;
        g_W1lo[n*HID + k] = __float2bfloat16(v - __bfloat162float(h));
    }
    int j = i - HID*HID;
    if (j >= 0 && j < NOUTP*HID) {
        int n = j >> 9, k = j & 511;
        float v = (n < NOUT) ? W2[k*NOUT + n] : 0.0f;
        __nv_bfloat16 h = __float2bfloat16(v);
        g_W2hi[n*HID + k] = h;
        g_W2lo[n*HID + k] = __float2bfloat16(v - __bfloat162float(h));
    }
}

__device__ __forceinline__ void mma16816(float* d, const uint32_t* a,
                                         const uint32_t* b)
{
    asm volatile(
        "mma.sync.aligned.m16n8k16.row.col.f32.bf16.bf16.f32 "
        "{%0,%1,%2,%3}, {%4,%5,%6,%7}, {%8,%9}, {%0,%1,%2,%3};\n"
        : "+f"(d[0]), "+f"(d[1]), "+f"(d[2]), "+f"(d[3])
        : "r"(a[0]), "r"(a[1]), "r"(a[2]), "r"(a[3]),
          "r"(b[0]), "r"(b[1]));
}

__device__ __forceinline__ void split_store2(__nv_bfloat16* Hh, __nv_bfloat16* Hl,
                                             int idx, float v0, float v1)
{
    __nv_bfloat162 hp = __floats2bfloat162_rn(v0, v1);
    float r0 = v0 - __bfloat162float(hp.x);
    float r1 = v1 - __bfloat162float(hp.y);
    __nv_bfloat162 lp = __floats2bfloat162_rn(r0, r1);
    *(__nv_bfloat162*)(Hh + idx) = hp;
    *(__nv_bfloat162*)(Hl + idx) = lp;
}

__global__ __launch_bounds__(TH, 1)
void ptpd_mma_kernel(const float* __restrict__ pts,
                     const float* __restrict__ W0, const float* __restrict__ b0,
                     const float* __restrict__ b1, const float* __restrict__ b2,
                     float* __restrict__ out)
{
    extern __shared__ char sm[];
    float*          Xs  = (float*)(sm + XS_OFF);
    __nv_bfloat16*  H0h = (__nv_bfloat16*)(sm + H0H_OFF);
    __nv_bfloat16*  H0l = (__nv_bfloat16*)(sm + H0L_OFF);
    __nv_bfloat16*  H1h = (__nv_bfloat16*)(sm + H1H_OFF);
    __nv_bfloat16*  H1l = (__nv_bfloat16*)(sm + H1L_OFF);
    __nv_bfloat16*  Wbh = (__nv_bfloat16*)(sm + WB_OFF);
    __nv_bfloat16*  Wbl = Wbh + NOUTP*WS;          // +10368 halfs
    float*          netS = (float*)(sm + WB_OFF);  // overlays Wbuf at the end

    const int tid  = threadIdx.x;
    const int lane = tid & 31;
    const int wid  = tid >> 5;
    const int g    = lane >> 2;    // 0..7
    const int t    = lane & 3;     // 0..3
    const int wm   = wid & 3;      // m-tile (16 rows each)
    const int wn   = wid >> 2;     // n half
    const long row0 = (long)blockIdx.x * TM;

    // ---------------- X tile ----------------
    for (int i = tid; i < TM*NIN; i += TH)
        Xs[i] = pts[row0*NIN + i];
    __syncthreads();

    // ---------------- layer 0 (scalar; 3% of FLOPs) ----------------
    {
        const int c0 = tid, c1 = tid + 256;
        float w0a[NIN], w0b[NIN];
        #pragma unroll
        for (int k = 0; k < NIN; k++) {
            w0a[k] = W0[k*HID + c0];
            w0b[k] = W0[k*HID + c1];
        }
        const float ba = b0[c0], bb = b0[c1];
        for (int r = 0; r < TM; r++) {
            float a = ba, b = bb;
            #pragma unroll
            for (int k = 0; k < NIN; k++) {
                const float x = Xs[r*NIN + k];
                a = fmaf(x, w0a[k], a);
                b = fmaf(x, w0b[k], b);
            }
            a = tanhf(a); b = tanhf(b);
            __nv_bfloat16 ah = __float2bfloat16(a);
            H0h[r*H0S + c0] = ah;
            H0l[r*H0S + c0] = __float2bfloat16(a - __bfloat162float(ah));
            __nv_bfloat16 bh = __float2bfloat16(b);
            H0h[r*H0S + c1] = bh;
            H0l[r*H0S + c1] = __float2bfloat16(b - __bfloat162float(bh));
        }
    }

    // layer-2 accumulators, bias-initialized (accumulate across the 4 k-chunks)
    float acc2[9][4];
    #pragma unroll
    for (int nt = 0; nt < 9; nt++) {
        int col = wn*72 + nt*8 + 2*t;
        float bv0 = (col     < NOUT) ? b2[col]     : 0.0f;
        float bv1 = (col + 1 < NOUT) ? b2[col + 1] : 0.0f;
        acc2[nt][0] = bv0; acc2[nt][1] = bv1;
        acc2[nt][2] = bv0; acc2[nt][3] = bv1;
    }

    const uint32_t* Ah0 = (const uint32_t*)H0h;
    const uint32_t* Al0 = (const uint32_t*)H0l;
    const uint32_t* Ah1 = (const uint32_t*)H1h;
    const uint32_t* Al1 = (const uint32_t*)H1l;
    const uint32_t* Bh  = (const uint32_t*)Wbh;
    const uint32_t* Bl  = (const uint32_t*)Wbl;

    // ================= chunks of 128 output cols of layer 1 =================
    for (int c = 0; c < 4; c++) {
        // layer-1 accumulators, bias-initialized
        float acc1[8][4];
        #pragma unroll
        for (int nt = 0; nt < 8; nt++) {
            int col = c*128 + wn*64 + nt*8 + 2*t;
            float bv0 = b1[col], bv1 = b1[col + 1];
            acc1[nt][0] = bv0; acc1[nt][1] = bv1;
            acc1[nt][2] = bv0; acc1[nt][3] = bv1;
        }

        // ---- layer 1: k in 8 slabs of 64 ----
        for (int ks = 0; ks < 8; ks++) {
            __syncthreads();                        // Wbuf free
            {   // stage W1 slab: n in [c*128,+128), k in [ks*64,+64)
                uint32_t* dH = (uint32_t*)Wbh;
                uint32_t* dL = (uint32_t*)Wbl;
                const uint32_t* sH = (const uint32_t*)g_W1hi;
                const uint32_t* sL = (const uint32_t*)g_W1lo;
                #pragma unroll
                for (int it = 0; it < 16; it++) {
                    int i = it*TH + tid;
                    int n = i >> 5, j = i & 31;
                    int gsrc = (c*128 + n)*256 + ks*32 + j;
                    int gdst = n*(WS/2) + j;
                    dH[gdst] = sH[gsrc];
                    dL[gdst] = sL[gsrc];
                }
            }
            __syncthreads();                        // slab visible

            #pragma unroll
            for (int kt = 0; kt < 4; kt++) {
                const int kk = ks*64 + kt*16;
                uint32_t ah[4], al[4];
                {
                    int ai = (wm*16 + g)*(H0S/2) + (kk >> 1) + t;
                    ah[0] = Ah0[ai];               ah[1] = Ah0[ai + 8*(H0S/2)];
                    ah[2] = Ah0[ai + 4];           ah[3] = Ah0[ai + 8*(H0S/2) + 4];
                    al[0] = Al0[ai];               al[1] = Al0[ai + 8*(H0S/2)];
                    al[2] = Al0[ai + 4];           al[3] = Al0[ai + 8*(H0S/2) + 4];
                }
                uint32_t bhf[8][2], blf[8][2];
                #pragma unroll
                for (int nt = 0; nt < 8; nt++) {
                    int n  = wn*64 + nt*8 + g;
                    int bi = n*(WS/2) + kt*8 + t;
                    bhf[nt][0] = Bh[bi]; bhf[nt][1] = Bh[bi + 4];
                    blf[nt][0] = Bl[bi]; blf[nt][1] = Bl[bi + 4];
                }
                #pragma unroll
                for (int nt = 0; nt < 8; nt++) mma16816(acc1[nt], ah, bhf[nt]);
                #pragma unroll
                for (int nt = 0; nt < 8; nt++) mma16816(acc1[nt], ah, blf[nt]);
                #pragma unroll
                for (int nt = 0; nt < 8; nt++) mma16816(acc1[nt], al, bhf[nt]);
            }
        }

        __syncthreads();     // all layer-1 MMAs done (Wbuf + prev H1 free)

        // ---- tanh + hi/lo split -> H1 chunk ----
        #pragma unroll
        for (int nt = 0; nt < 8; nt++) {
            int coll = wn*64 + nt*8 + 2*t;
            int r    = wm*16 + g;
            split_store2(H1h, H1l, r*H1S + coll,
                         tanhf(acc1[nt][0]), tanhf(acc1[nt][1]));
            split_store2(H1h, H1l, (r + 8)*H1S + coll,
                         tanhf(acc1[nt][2]), tanhf(acc1[nt][3]));
        }
        __syncthreads();     // H1 chunk visible

        // ---- layer 2 partial: k = this chunk's 128 cols, 2 slabs of 64 ----
        for (int ks2 = 0; ks2 < 2; ks2++) {
            {   // stage W2 slab: n in [0,144), k in [c*128 + ks2*64, +64)
                uint32_t* dH = (uint32_t*)Wbh;
                uint32_t* dL = (uint32_t*)Wbl;
                const uint32_t* sH = (const uint32_t*)g_W2hi;
                const uint32_t* sL = (const uint32_t*)g_W2lo;
                #pragma unroll
                for (int it = 0; it < 18; it++) {
                    int i = it*TH + tid;
                    int n = i >> 5, j = i & 31;
                    int gsrc = n*256 + c*64 + ks2*32 + j;
                    int gdst = n*(WS/2) + j;
                    dH[gdst] = sH[gsrc];
                    dL[gdst] = sL[gsrc];
                }
            }
            __syncthreads();                        // slab visible

            #pragma unroll
            for (int kt = 0; kt < 4; kt++) {
                const int kl = ks2*64 + kt*16;      // k local within chunk
                uint32_t ah[4], al[4];
                {
                    int ai = (wm*16 + g)*(H1S/2) + (kl >> 1) + t;
                    ah[0] = Ah1[ai];               ah[1] = Ah1[ai + 8*(H1S/2)];
                    ah[2] = Ah1[ai + 4];           ah[3] = Ah1[ai + 8*(H1S/2) + 4];
                    al[0] = Al1[ai];               al[1] = Al1[ai + 8*(H1S/2)];
                    al[2] = Al1[ai + 4];           al[3] = Al1[ai + 8*(H1S/2) + 4];
                }
                uint32_t bhf[9][2], blf[9][2];
                #pragma unroll
                for (int nt = 0; nt < 9; nt++) {
                    int n  = wn*72 + nt*8 + g;
                    int bi = n*(WS/2) + kt*8 + t;
                    bhf[nt][0] = Bh[bi]; bhf[nt][1] = Bh[bi + 4];
                    blf[nt][0] = Bl[bi]; blf[nt][1] = Bl[bi + 4];
                }
                #pragma unroll
                for (int nt = 0; nt < 9; nt++) mma16816(acc2[nt], ah, bhf[nt]);
                #pragma unroll
                for (int nt = 0; nt < 9; nt++) mma16816(acc2[nt], ah, blf[nt]);
                #pragma unroll
                for (int nt = 0; nt < 9; nt++) mma16816(acc2[nt], al, bhf[nt]);
            }
            __syncthreads();                        // MMAs done before restage
        }
    }

    // ---- net -> smem (overlays Wbuf; last barrier above protects it) ----
    #pragma unroll
    for (int nt = 0; nt < 9; nt++) {
        int col = wn*72 + nt*8 + 2*t;
        int r   = wm*16 + g;
        netS[r*NETS + col]           = acc2[nt][0];
        netS[r*NETS + col + 1]       = acc2[nt][1];
        netS[(r + 8)*NETS + col]     = acc2[nt][2];
        netS[(r + 8)*NETS + col + 1] = acc2[nt][3];
    }
    __syncthreads();

    // ---- quadratic form: val = ||M^T x||^2 + eps*||x||^2 ----
    if (tid < TM) {
        const float* nn = netS + tid*NETS;
        const float* xv = Xs + tid*NIN;
        float x[NIN], sx = 0.0f;
        #pragma unroll
        for (int i = 0; i < NIN; i++) { x[i] = xv[i]; sx = fmaf(x[i], x[i], sx); }
        float y[NIN];
        #pragma unroll
        for (int j = 0; j < NIN; j++) y[j] = 0.0f;
        int tt = 0;
        #pragma unroll
        for (int i = 0; i < NIN; i++) {
            #pragma unroll
            for (int j = 0; j <= i; j++) {
                y[j] = fmaf(nn[tt], x[i], y[j]);
                tt++;
            }
        }
        float v = 0.0f;
        #pragma unroll
        for (int j = 0; j < NIN; j++) v = fmaf(y[j], y[j], v);
        out[row0 + tid] = v + 1e-6f * sx;
    }
}

extern "C" void kernel_launch(void* const* d_in, const int* in_sizes, int n_in,
                              void* d_out, int out_size)
{
    const float* pts = (const float*)d_in[0];
    const float* W0  = (const float*)d_in[1];
    const float* b0  = (const float*)d_in[2];
    const float* W1  = (const float*)d_in[3];
    const float* b1  = (const float*)d_in[4];
    const float* W2  = (const float*)d_in[5];
    const float* b2  = (const float*)d_in[6];
    float* out = (float*)d_out;

    const int B = in_sizes[0] / NIN;

    cudaFuncSetAttribute(ptpd_mma_kernel,
                         cudaFuncAttributeMaxDynamicSharedMemorySize, SMEM_BYTES);

    const int prep_elems = HID*HID + NOUTP*HID;
    prep_weights<<<(prep_elems + 255)/256, 256>>>(W1, W2);

    ptpd_mma_kernel<<<B/TM, TH, SMEM_BYTES>>>(pts, W0, b0, b1, b2, out);
}